// round 3
// baseline (speedup 1.0000x reference)
#include <cuda_runtime.h>

#define TT 128
#define BB 256
#define FF 76
#define HH 64

// scratch: __device__ globals (allowed; no runtime allocation)
__device__ float g_hs[(size_t)FF * TT * HH * BB];   // (F, T, H, B) ~638 MB
__device__ float g_emb[BB * FF * HH];               // (B, F, H)

__device__ __forceinline__ float sigf(float x) {
    return __fdividef(1.f, 1.f + __expf(-x));
}
__device__ __forceinline__ float tanhf_(float x) {
    return __fdividef(2.f, 1.f + __expf(-2.f * x)) - 1.f;
}

// ---------------------------------------------------------------------------
// Kernel 1: per-feature GRU scan. CTA = (f, 32-batch group). 8 warps, each
// owns 8 of the 192 gate rows. h state ping-pongs in smem; 1 barrier/step.
// ---------------------------------------------------------------------------
__global__ void __launch_bounds__(256)
gru_kernel(const float* __restrict__ x, const float* __restrict__ w_ih,
           const float* __restrict__ w_hh, const float* __restrict__ b_ih,
           const float* __restrict__ b_hh)
{
    extern __shared__ float sm[];
    float* Whh = sm;            // 192*64
    float* wih = sm + 12288;    // 192
    float* bih = wih + 192;
    float* bhh = bih + 192;
    float* hb0 = bhh + 192;     // 64*32
    float* hb1 = hb0 + 2048;

    int unit = blockIdx.x;
    int f = unit >> 3, bg = unit & 7;
    int tid = threadIdx.x, warp = tid >> 5, lane = tid & 31;

    const float4* wsrc = (const float4*)(w_hh + (size_t)f * 12288);
    for (int i = tid; i < 3072; i += 256) ((float4*)Whh)[i] = wsrc[i];
    for (int i = tid; i < 192; i += 256) {
        wih[i] = w_ih[f * 192 + i];
        bih[i] = b_ih[f * 192 + i];
        bhh[i] = b_hh[f * 192 + i];
    }
    for (int i = tid; i < 2048; i += 256) hb0[i] = 0.f;
    __syncthreads();

    int j0 = warp * 8;
    int b  = bg * 32 + lane;
    const float* xp = x + b * FF + f;                        // x[t][b][f]
    float* hsp = g_hs + (size_t)f * TT * HH * BB + b;

    float* cur = hb0;
    float* nxt = hb1;

    for (int t = 0; t < TT; t++) {
        float xv = __ldg(xp + (size_t)t * (BB * FF));
        float ar[8], az[8], an[8];
#pragma unroll
        for (int jj = 0; jj < 8; jj++) { ar[jj] = 0.f; az[jj] = 0.f; an[jj] = 0.f; }

#pragma unroll 4
        for (int hb = 0; hb < 16; hb++) {
            int h4 = hb * 4;
            float hv0 = cur[(h4 + 0) * 32 + lane];
            float hv1 = cur[(h4 + 1) * 32 + lane];
            float hv2 = cur[(h4 + 2) * 32 + lane];
            float hv3 = cur[(h4 + 3) * 32 + lane];
#pragma unroll
            for (int jj = 0; jj < 8; jj++) {
                int j = j0 + jj;
                float4 wr = *(const float4*)(Whh + j * 64 + h4);
                ar[jj] = fmaf(hv0, wr.x, ar[jj]); ar[jj] = fmaf(hv1, wr.y, ar[jj]);
                ar[jj] = fmaf(hv2, wr.z, ar[jj]); ar[jj] = fmaf(hv3, wr.w, ar[jj]);
                float4 wz = *(const float4*)(Whh + (64 + j) * 64 + h4);
                az[jj] = fmaf(hv0, wz.x, az[jj]); az[jj] = fmaf(hv1, wz.y, az[jj]);
                az[jj] = fmaf(hv2, wz.z, az[jj]); az[jj] = fmaf(hv3, wz.w, az[jj]);
                float4 wn = *(const float4*)(Whh + (128 + j) * 64 + h4);
                an[jj] = fmaf(hv0, wn.x, an[jj]); an[jj] = fmaf(hv1, wn.y, an[jj]);
                an[jj] = fmaf(hv2, wn.z, an[jj]); an[jj] = fmaf(hv3, wn.w, an[jj]);
            }
        }

        float* hso = hsp + (size_t)t * (HH * BB);
#pragma unroll
        for (int jj = 0; jj < 8; jj++) {
            int j = j0 + jj;
            float r = sigf(fmaf(xv, wih[j], bih[j]) + ar[jj] + bhh[j]);
            float z = sigf(fmaf(xv, wih[64 + j], bih[64 + j]) + az[jj] + bhh[64 + j]);
            float n = tanhf_(fmaf(xv, wih[128 + j], bih[128 + j]) + r * (an[jj] + bhh[128 + j]));
            float hold = cur[j * 32 + lane];
            float hn = n + z * (hold - n);
            nxt[j * 32 + lane] = hn;
            hso[j * BB] = hn;
        }
        float* tp = cur; cur = nxt; nxt = tp;
        __syncthreads();
    }
}

// ---------------------------------------------------------------------------
// Kernel 2: per-feature time attention, single streaming pass over hs.
// CTA = (f, 32-batch group). dp_t = u . h_t with u = Wx (Wt^T h_last).
// ---------------------------------------------------------------------------
__global__ void __launch_bounds__(256)
attn_kernel(const float* __restrict__ Wt, const float* __restrict__ Wx,
            const float* __restrict__ rate)
{
    __shared__ float sWt[512], sWx[512];
    __shared__ float sPq[8][32][8];
    __shared__ float sQ[32][8];
    __shared__ float sDp[8][32];
    __shared__ float sE[32];

    int f = blockIdx.x >> 3, bg = blockIdx.x & 7;
    int tid = threadIdx.x, w = tid >> 5, lane = tid & 31;
    int b = bg * 32 + lane;

    for (int i = tid; i < 512; i += 256) { sWt[i] = Wt[f * 512 + i]; sWx[i] = Wx[f * 512 + i]; }
    __syncthreads();

    const float* base = g_hs + (size_t)f * TT * HH * BB;

    // h_last and q partials
    const float* hlp = base + (size_t)(TT - 1) * HH * BB;
    float hl[8];
#pragma unroll
    for (int k = 0; k < 8; k++) hl[k] = hlp[(w * 8 + k) * BB + b];
    float pq[8];
#pragma unroll
    for (int a = 0; a < 8; a++) pq[a] = 0.f;
#pragma unroll
    for (int k = 0; k < 8; k++)
#pragma unroll
        for (int a = 0; a < 8; a++) pq[a] = fmaf(hl[k], sWt[(w * 8 + k) * 8 + a], pq[a]);
#pragma unroll
    for (int a = 0; a < 8; a++) sPq[w][lane][a] = pq[a];
    __syncthreads();
    if (w == 0) {
#pragma unroll
        for (int a = 0; a < 8; a++) {
            float q = 0.f;
#pragma unroll
            for (int ww = 0; ww < 8; ww++) q += sPq[ww][lane][a];
            sQ[lane][a] = q;
        }
    }
    __syncthreads();

    float u[8];
#pragma unroll
    for (int k = 0; k < 8; k++) {
        float acc = 0.f;
#pragma unroll
        for (int a = 0; a < 8; a++) acc = fmaf(sWx[(w * 8 + k) * 8 + a], sQ[lane][a], acc);
        u[k] = acc;
    }

    float rsig = sigf(__ldg(rate + f));
    float ssum = 0.f;
    float acc[8];
#pragma unroll
    for (int k = 0; k < 8; k++) acc[k] = 0.f;

    for (int t = 0; t < TT; t++) {
        const float* hp = base + (size_t)t * HH * BB;
        float hv[8];
#pragma unroll
        for (int k = 0; k < 8; k++) hv[k] = hp[(w * 8 + k) * BB + b];
        float pdp = 0.f;
#pragma unroll
        for (int k = 0; k < 8; k++) pdp = fmaf(u[k], hv[k], pdp);
        sDp[w][lane] = pdp;
        __syncthreads();
        if (w == 0) {
            float dp = 0.f;
#pragma unroll
            for (int ww = 0; ww < 8; ww++) dp += sDp[ww][lane];
            float sig = sigf(dp);
            float denom = rsig * __logf(2.72f + (1.f - sig)) * (float)(TT - t);
            float e = fmaxf(__fdividef(sig, denom), 0.f);
            sE[lane] = __expf(e);
        }
        __syncthreads();
        float ew = sE[lane];
        ssum += ew;
#pragma unroll
        for (int k = 0; k < 8; k++) acc[k] = fmaf(ew, hv[k], acc[k]);
    }

    float inv = __fdividef(1.f, ssum);
#pragma unroll
    for (int k = 0; k < 8; k++)
        g_emb[(b * FF + f) * HH + w * 8 + k] = acc[k] * inv;
}

// ---------------------------------------------------------------------------
// Kernel 3: MHA over F + FFN + FinalAttentionQKV + output head. CTA = batch b.
// Everything lives in dynamic smem (~135 KB).
// ---------------------------------------------------------------------------
__global__ void __launch_bounds__(256)
mha_kernel(const float* __restrict__ wq, const float* __restrict__ bq,
           const float* __restrict__ wk, const float* __restrict__ bk,
           const float* __restrict__ wv, const float* __restrict__ bv,
           const float* __restrict__ wo, const float* __restrict__ bo,
           const float* __restrict__ fw1, const float* __restrict__ fb1,
           const float* __restrict__ fw2, const float* __restrict__ fb2,
           const float* __restrict__ faq, const float* __restrict__ fabq,
           const float* __restrict__ fak, const float* __restrict__ fabk,
           const float* __restrict__ fav, const float* __restrict__ fabv,
           const float* __restrict__ o0w, const float* __restrict__ o0b,
           const float* __restrict__ o1w, const float* __restrict__ o1b,
           float* __restrict__ out)
{
    extern __shared__ float sm[];
    float* sE  = sm;            // 4864 emb / residual base
    float* sA  = sm + 4864;     // 4864
    float* sB  = sm + 9728;     // 4864
    float* sC  = sm + 14592;    // 4864
    float* sW  = sm + 19456;    // 4096
    float* sW2 = sm + 23552;    // 4096
    float* sS  = sm + 27648;    // 5776 scores
    float* sFq = sm + 33424;    // 64
    float* sFe = sm + 33488;    // 80
    float* sV  = sm + 33568;    // 64
    float* sR  = sm + 33632;    // 64

    int b = blockIdx.x, tid = threadIdx.x;

    for (int i = tid; i < 4864; i += 256) sE[i] = g_emb[b * 4864 + i];

    auto loadW = [&](float* dst, const float* src) {
        for (int i = tid; i < 4096; i += 256) dst[i] = __ldg(src + i);
    };
    auto lin = [&](const float* in, const float* W, const float* bias,
                   float* op, const float* resid) {
        for (int idx = tid; idx < 4864; idx += 256) {
            int f = idx >> 6, h = idx & 63;
            float acc = __ldg(bias + h);
            const float* ip = in + f * 64;
#pragma unroll 8
            for (int k = 0; k < 64; k++) acc = fmaf(ip[k], W[k * 64 + h], acc);
            if (resid) acc += resid[idx];
            op[idx] = acc;
        }
    };

    loadW(sW, wq); __syncthreads();
    lin(sE, sW, bq, sA, nullptr); __syncthreads();
    loadW(sW, wk); __syncthreads();
    lin(sE, sW, bk, sB, nullptr); __syncthreads();
    loadW(sW, wv); __syncthreads();
    lin(sE, sW, bv, sC, nullptr); __syncthreads();

    // heads: Q=sA K=sB V=sC; ctx overwrites sA slice per head
    for (int hd = 0; hd < 4; hd++) {
        int off = hd * 16;
        for (int idx = tid; idx < 5776; idx += 256) {
            int fq = idx / 76, fk = idx - fq * 76;
            float acc = 0.f;
#pragma unroll
            for (int d = 0; d < 16; d++)
                acc = fmaf(sA[fq * 64 + off + d], sB[fk * 64 + off + d], acc);
            sS[idx] = acc * 0.25f;
        }
        __syncthreads();
        if (tid < 76) {
            float m = -1e30f;
            for (int j = 0; j < 76; j++) m = fmaxf(m, sS[tid * 76 + j]);
            float s = 0.f;
            for (int j = 0; j < 76; j++) {
                float e = __expf(sS[tid * 76 + j] - m);
                sS[tid * 76 + j] = e; s += e;
            }
            float inv = __fdividef(1.f, s);
            for (int j = 0; j < 76; j++) sS[tid * 76 + j] *= inv;
        }
        __syncthreads();
        for (int idx = tid; idx < 1216; idx += 256) {
            int fq = idx >> 4, d = idx & 15;
            float acc = 0.f;
            for (int fk = 0; fk < 76; fk++)
                acc = fmaf(sS[fq * 76 + fk], sC[fk * 64 + off + d], acc);
            sA[fq * 64 + off + d] = acc;
        }
        __syncthreads();
    }

    // ctx = emb + ctx_mh @ wo + bo  -> sB
    loadW(sW, wo); __syncthreads();
    lin(sA, sW, bo, sB, sE); __syncthreads();

    // FFN with residual base sB, accumulate into sC
    for (int idx = tid; idx < 4864; idx += 256)
        sC[idx] = sB[idx] + __ldg(fb2 + (idx & 63));
    for (int c = 0; c < 4; c++) {
        for (int i = tid; i < 4096; i += 256) {
            int k = i >> 6, j = i & 63;
            sW[i]  = __ldg(fw1 + k * 256 + c * 64 + j);
            sW2[i] = __ldg(fw2 + (c * 64 + k) * 64 + j);
        }
        __syncthreads();
        for (int idx = tid; idx < 4864; idx += 256) {
            int f = idx >> 6, j = idx & 63;
            float acc = __ldg(fb1 + c * 64 + j);
            const float* ip = sB + f * 64;
#pragma unroll 8
            for (int k = 0; k < 64; k++) acc = fmaf(ip[k], sW[k * 64 + j], acc);
            sA[idx] = fmaxf(acc, 0.f);
        }
        __syncthreads();
        for (int idx = tid; idx < 4864; idx += 256) {
            int f = idx >> 6, h = idx & 63;
            float acc = 0.f;
            const float* ip = sA + f * 64;
#pragma unroll 8
            for (int j = 0; j < 64; j++) acc = fmaf(ip[j], sW2[j * 64 + h], acc);
            sC[idx] += acc;
        }
        __syncthreads();
    }

    // FinalAttentionQKV ('mul') on sC
    if (tid < 64) {
        float acc = __ldg(fabq + tid);
        for (int k = 0; k < 64; k++)
            acc = fmaf(sC[75 * 64 + k], __ldg(faq + k * 64 + tid), acc);
        sFq[tid] = acc;
    }
    loadW(sW, fak); __syncthreads();
    lin(sC, sW, fabk, sA, nullptr); __syncthreads();
    loadW(sW, fav); __syncthreads();
    lin(sC, sW, fabv, sB, nullptr); __syncthreads();

    if (tid < 76) {
        float acc = 0.f;
        for (int h = 0; h < 64; h++) acc = fmaf(sA[tid * 64 + h], sFq[h], acc);
        sFe[tid] = acc;
    }
    __syncthreads();
    if (tid == 0) {
        float m = -1e30f;
        for (int f2 = 0; f2 < 76; f2++) m = fmaxf(m, sFe[f2]);
        float s = 0.f;
        for (int f2 = 0; f2 < 76; f2++) {
            float e = __expf(sFe[f2] - m); sFe[f2] = e; s += e;
        }
        sFe[76] = __fdividef(1.f, s);
    }
    __syncthreads();
    if (tid < 64) {
        float acc = 0.f;
        for (int f2 = 0; f2 < 76; f2++) acc = fmaf(sFe[f2], sB[f2 * 64 + tid], acc);
        sV[tid] = acc * sFe[76];
    }
    __syncthreads();
    if (tid < 64) {
        float acc = __ldg(o0b + tid);
        for (int k = 0; k < 64; k++) acc = fmaf(sV[k], __ldg(o0w + k * 64 + tid), acc);
        sR[tid] = fmaxf(acc, 0.f);
    }
    __syncthreads();
    if (tid == 0) {
        float acc = __ldg(o1b);
        for (int h = 0; h < 64; h++) acc = fmaf(sR[h], __ldg(o1w + h), acc);
        out[b] = sigf(acc);
    }
}

// ---------------------------------------------------------------------------
extern "C" void kernel_launch(void* const* d_in, const int* in_sizes, int n_in,
                              void* d_out, int out_size)
{
    const float* x      = (const float*)d_in[0];
    const float* w_ih   = (const float*)d_in[1];
    const float* w_hh   = (const float*)d_in[2];
    const float* b_ih   = (const float*)d_in[3];
    const float* b_hh   = (const float*)d_in[4];
    const float* att_Wt = (const float*)d_in[5];
    const float* att_Wx = (const float*)d_in[6];
    const float* att_rt = (const float*)d_in[7];
    const float* mwq = (const float*)d_in[8];   const float* mbq = (const float*)d_in[9];
    const float* mwk = (const float*)d_in[10];  const float* mbk = (const float*)d_in[11];
    const float* mwv = (const float*)d_in[12];  const float* mbv = (const float*)d_in[13];
    const float* mwo = (const float*)d_in[14];  const float* mbo = (const float*)d_in[15];
    const float* fw1 = (const float*)d_in[16];  const float* fb1 = (const float*)d_in[17];
    const float* fw2 = (const float*)d_in[18];  const float* fb2 = (const float*)d_in[19];
    const float* faq = (const float*)d_in[20];  const float* fabq = (const float*)d_in[21];
    const float* fak = (const float*)d_in[22];  const float* fabk = (const float*)d_in[23];
    const float* fav = (const float*)d_in[24];  const float* fabv = (const float*)d_in[25];
    const float* o0w = (const float*)d_in[26];  const float* o0b = (const float*)d_in[27];
    const float* o1w = (const float*)d_in[28];  const float* o1b = (const float*)d_in[29];
    float* out = (float*)d_out;

    cudaFuncSetAttribute(gru_kernel, cudaFuncAttributeMaxDynamicSharedMemorySize, 69632);
    cudaFuncSetAttribute(mha_kernel, cudaFuncAttributeMaxDynamicSharedMemorySize, 139264);

    gru_kernel<<<FF * 8, 256, 67840>>>(x, w_ih, w_hh, b_ih, b_hh);
    attn_kernel<<<FF * 8, 256>>>(att_Wt, att_Wx, att_rt);
    mha_kernel<<<BB, 256, 134784>>>(mwq, mbq, mwk, mbk, mwv, mbv, mwo, mbo,
                                    fw1, fb1, fw2, fb2,
                                    faq, fabq, fak, fabk, fav, fabv,
                                    o0w, o0b, o1w, o1b, out);
}

// round 5
// speedup vs baseline: 1.4917x; 1.4917x over previous
#include <cuda_runtime.h>
#include <cuda_bf16.h>
#include <cstdint>

#define TT 128
#define BB 256
#define FF 76
#define HH 64

__device__ float g_hs[(size_t)FF * TT * HH * BB];   // (F, T, H, B)
__device__ float g_emb[BB * FF * HH];               // (B, F, H)

__device__ __forceinline__ float sigf(float x) {
    return __fdividef(1.f, 1.f + __expf(-x));
}
__device__ __forceinline__ float tanhf_(float x) {
    return __fdividef(2.f, 1.f + __expf(-2.f * x)) - 1.f;
}
__device__ __forceinline__ unsigned short bfbits(float x) {
    __nv_bfloat16 b = __float2bfloat16(x);
    return *(unsigned short*)&b;
}
__device__ __forceinline__ float bffloat(unsigned short u) {
    __nv_bfloat16 b = *(__nv_bfloat16*)&u;
    return __bfloat162float(b);
}
__device__ __forceinline__ void mma_bf16(float* d, const uint32_t* a,
                                         uint32_t b0, uint32_t b1) {
    asm volatile("mma.sync.aligned.m16n8k16.row.col.f32.bf16.bf16.f32 "
        "{%0,%1,%2,%3}, {%4,%5,%6,%7}, {%8,%9}, {%0,%1,%2,%3};"
        : "+f"(d[0]), "+f"(d[1]), "+f"(d[2]), "+f"(d[3])
        : "r"(a[0]), "r"(a[1]), "r"(a[2]), "r"(a[3]), "r"(b0), "r"(b1));
}

// smem byte offsets (dynamic)
#define OFF_WHI 0
#define OFF_WLO 27648
#define OFF_HHI 55296
#define OFF_HLO 92160
#define OFF_CC  129024
#define GRU_SMEM 130816

// ---------------------------------------------------------------------------
// Kernel 1: GRU via mma.sync bf16 3-term fp32 emulation. CTA = feature.
// Warp w owns batch rows [32w, 32w+32) as 2 m16 tiles. Per step:
//   load A-frags (h hi/lo) -> bar -> 8 j-chunks { 72 mma + gate epilogue +
//   h_s pair write + g_hs store } -> bar.
// ---------------------------------------------------------------------------
__global__ void __launch_bounds__(256, 1)
gru_mma(const float* __restrict__ x, const float* __restrict__ w_ih,
        const float* __restrict__ w_hh, const float* __restrict__ b_ih,
        const float* __restrict__ b_hh)
{
    extern __shared__ char base[];
    unsigned short* Wh16 = (unsigned short*)(base + OFF_WHI);
    unsigned short* Wl16 = (unsigned short*)(base + OFF_WLO);
    uint32_t* Whw = (uint32_t*)(base + OFF_WHI);
    uint32_t* Wlw = (uint32_t*)(base + OFF_WLO);
    uint32_t* Hhw = (uint32_t*)(base + OFF_HHI);
    uint32_t* Hlw = (uint32_t*)(base + OFF_HLO);
    float* Cc = (float*)(base + OFF_CC);

    const int f = blockIdx.x, tid = threadIdx.x;
    const int w = tid >> 5, lane = tid & 31;
    const int r0 = lane >> 2, c = lane & 3;
    const int Mb = w * 32;

    // stage W hi/lo (stride 72 bf16 = 36 words)
    for (int i = tid; i < 12288; i += 256) {
        int n = i >> 6, k = i & 63;
        float wv = w_hh[((size_t)f * 192 + n) * 64 + k];
        unsigned short hb = bfbits(wv);
        unsigned short lb = bfbits(wv - bffloat(hb));
        Wh16[n * 72 + k] = hb;
        Wl16[n * 72 + k] = lb;
    }
    // zero h planes (contiguous 73728 B = 18432 words)
    for (int i = tid; i < 18432; i += 256) Hhw[i] = 0u;
    if (tid < 64) {
        Cc[tid]       = w_ih[f * 192 + tid];
        Cc[64 + tid]  = b_ih[f * 192 + tid] + b_hh[f * 192 + tid];
        Cc[128 + tid] = w_ih[f * 192 + 64 + tid];
        Cc[192 + tid] = b_ih[f * 192 + 64 + tid] + b_hh[f * 192 + 64 + tid];
        Cc[256 + tid] = w_ih[f * 192 + 128 + tid];
        Cc[320 + tid] = b_ih[f * 192 + 128 + tid];
        Cc[384 + tid] = b_hh[f * 192 + 128 + tid];
    }
    __syncthreads();

    float* hsf = g_hs + (size_t)f * TT * HH * BB;

    for (int t = 0; t < TT; t++) {
        // x values for this thread's 4 batch rows
        float xv4[4];
#pragma unroll
        for (int p = 0; p < 4; p++) {
            int b = Mb + r0 + p * 8;
            xv4[p] = __ldg(x + ((size_t)t * BB + b) * FF + f);
        }
        // A fragments: [plane][mtile][ktile][reg]
        uint32_t ah[2][4][4], al[2][4][4];
#pragma unroll
        for (int m = 0; m < 2; m++) {
            int b0 = Mb + m * 16 + r0;
#pragma unroll
            for (int kt = 0; kt < 4; kt++) {
                int w0 = b0 * 36 + 8 * kt + c;
                int w1 = (b0 + 8) * 36 + 8 * kt + c;
                ah[m][kt][0] = Hhw[w0];     ah[m][kt][1] = Hhw[w1];
                ah[m][kt][2] = Hhw[w0 + 4]; ah[m][kt][3] = Hhw[w1 + 4];
                al[m][kt][0] = Hlw[w0];     al[m][kt][1] = Hlw[w1];
                al[m][kt][2] = Hlw[w0 + 4]; al[m][kt][3] = Hlw[w1 + 4];
            }
        }
        __syncthreads();

        float* hst = hsf + (size_t)t * (HH * BB);
#pragma unroll 2
        for (int tc = 0; tc < 8; tc++) {
            float d[2][3][4];
#pragma unroll
            for (int m = 0; m < 2; m++)
#pragma unroll
                for (int g = 0; g < 3; g++)
#pragma unroll
                    for (int q = 0; q < 4; q++) d[m][g][q] = 0.f;

#pragma unroll
            for (int g = 0; g < 3; g++) {
                int nrow = g * 64 + 8 * tc + r0;
#pragma unroll
                for (int kt = 0; kt < 4; kt++) {
                    int wo = nrow * 36 + 8 * kt + c;
                    uint32_t bh0 = Whw[wo], bh1 = Whw[wo + 4];
                    uint32_t bl0 = Wlw[wo], bl1 = Wlw[wo + 4];
#pragma unroll
                    for (int m = 0; m < 2; m++) {
                        mma_bf16(d[m][g], ah[m][kt], bh0, bh1);
                        mma_bf16(d[m][g], ah[m][kt], bl0, bl1);
                        mma_bf16(d[m][g], al[m][kt], bh0, bh1);
                    }
                }
            }
            // epilogue: thread owns (b, j) pairs matching D layout
#pragma unroll
            for (int m = 0; m < 2; m++) {
#pragma unroll
                for (int rg = 0; rg < 2; rg++) {
                    int b = Mb + m * 16 + r0 + rg * 8;
                    float xv = xv4[m * 2 + rg];
                    int pw = b * 36 + 4 * tc + c;
                    uint32_t ph = Hhw[pw], pl = Hlw[pw];
                    float hn2[2];
#pragma unroll
                    for (int e = 0; e < 2; e++) {
                        int j = 8 * tc + 2 * c + e;
                        float dr = d[m][0][rg * 2 + e];
                        float dz = d[m][1][rg * 2 + e];
                        float dn = d[m][2][rg * 2 + e];
                        float rv = sigf(fmaf(xv, Cc[j], Cc[64 + j]) + dr);
                        float zv = sigf(fmaf(xv, Cc[128 + j], Cc[192 + j]) + dz);
                        float nv = tanhf_(fmaf(xv, Cc[256 + j], Cc[320 + j]) +
                                          rv * (dn + Cc[384 + j]));
                        unsigned short hu = e ? (unsigned short)(ph >> 16)
                                              : (unsigned short)(ph & 0xffff);
                        unsigned short lu = e ? (unsigned short)(pl >> 16)
                                              : (unsigned short)(pl & 0xffff);
                        float hold = bffloat(hu) + bffloat(lu);
                        float hn = nv + zv * (hold - nv);
                        hn2[e] = hn;
                        hst[(size_t)j * BB + b] = hn;
                    }
                    unsigned short h0 = bfbits(hn2[0]);
                    unsigned short h1 = bfbits(hn2[1]);
                    unsigned short l0 = bfbits(hn2[0] - bffloat(h0));
                    unsigned short l1 = bfbits(hn2[1] - bffloat(h1));
                    Hhw[pw] = (uint32_t)h0 | ((uint32_t)h1 << 16);
                    Hlw[pw] = (uint32_t)l0 | ((uint32_t)l1 << 16);
                }
            }
        }
        __syncthreads();
    }
}

// ---------------------------------------------------------------------------
// Kernel 2: time attention, barrier-free. lane = (batch%16, h-half); dp via
// shfl.xor(16). grid = FF*2 (128 batches per CTA).
// ---------------------------------------------------------------------------
__global__ void __launch_bounds__(256)
attn2(const float* __restrict__ Wt, const float* __restrict__ Wx,
      const float* __restrict__ rate)
{
    int f = blockIdx.x >> 1, half = blockIdx.x & 1;
    int tid = threadIdx.x, w = tid >> 5, lane = tid & 31;
    int b = half * 128 + w * 16 + (lane & 15);
    int j0 = (lane >> 4) * 32;
    const float* base = g_hs + (size_t)f * TT * HH * BB;

    float q[8];
    {
        float hl[32];
        const float* hp = base + (size_t)(TT - 1) * HH * BB + b;
#pragma unroll
        for (int k = 0; k < 32; k++) hl[k] = hp[(size_t)(j0 + k) * BB];
#pragma unroll
        for (int a = 0; a < 8; a++) {
            float acc = 0.f;
#pragma unroll
            for (int k = 0; k < 32; k++)
                acc = fmaf(hl[k], __ldg(Wt + ((size_t)f * 64 + j0 + k) * 8 + a), acc);
            q[a] = acc + __shfl_xor_sync(0xffffffffu, acc, 16);
        }
    }
    float u[32];
#pragma unroll
    for (int k = 0; k < 32; k++) {
        float acc = 0.f;
#pragma unroll
        for (int a = 0; a < 8; a++)
            acc = fmaf(__ldg(Wx + ((size_t)f * 64 + j0 + k) * 8 + a), q[a], acc);
        u[k] = acc;
    }
    float rsig = sigf(__ldg(rate + f));
    float ssum = 0.f, acc[32];
#pragma unroll
    for (int k = 0; k < 32; k++) acc[k] = 0.f;

    for (int t = 0; t < TT; t++) {
        const float* hp = base + (size_t)t * HH * BB + b;
        float hv[32];
#pragma unroll
        for (int k = 0; k < 32; k++) hv[k] = hp[(size_t)(j0 + k) * BB];
        float dp = 0.f;
#pragma unroll
        for (int k = 0; k < 32; k++) dp = fmaf(u[k], hv[k], dp);
        dp += __shfl_xor_sync(0xffffffffu, dp, 16);
        float sig = sigf(dp);
        float e = fmaxf(__fdividef(sig,
                    rsig * __logf(2.72f + (1.f - sig)) * (float)(TT - t)), 0.f);
        float ew = __expf(e);
        ssum += ew;
#pragma unroll
        for (int k = 0; k < 32; k++) acc[k] = fmaf(ew, hv[k], acc[k]);
    }
    float inv = __fdividef(1.f, ssum);
#pragma unroll
    for (int k = 0; k < 32; k++)
        g_emb[(b * FF + f) * HH + j0 + k] = acc[k] * inv;
}

// ---------------------------------------------------------------------------
// Kernel 3: MHA over F + FFN + FinalAttentionQKV + head. CTA = batch.
// ---------------------------------------------------------------------------
__global__ void __launch_bounds__(256)
mha_kernel(const float* __restrict__ wq, const float* __restrict__ bq,
           const float* __restrict__ wk, const float* __restrict__ bk,
           const float* __restrict__ wv, const float* __restrict__ bv,
           const float* __restrict__ wo, const float* __restrict__ bo,
           const float* __restrict__ fw1, const float* __restrict__ fb1,
           const float* __restrict__ fw2, const float* __restrict__ fb2,
           const float* __restrict__ faq, const float* __restrict__ fabq,
           const float* __restrict__ fak, const float* __restrict__ fabk,
           const float* __restrict__ fav, const float* __restrict__ fabv,
           const float* __restrict__ o0w, const float* __restrict__ o0b,
           const float* __restrict__ o1w, const float* __restrict__ o1b,
           float* __restrict__ out)
{
    extern __shared__ float sm[];
    float* sE  = sm;
    float* sA  = sm + 4864;
    float* sB  = sm + 9728;
    float* sC  = sm + 14592;
    float* sW  = sm + 19456;
    float* sW2 = sm + 23552;
    float* sS  = sm + 27648;
    float* sFq = sm + 33424;
    float* sFe = sm + 33488;
    float* sV  = sm + 33568;
    float* sR  = sm + 33632;

    int b = blockIdx.x, tid = threadIdx.x;
    for (int i = tid; i < 4864; i += 256) sE[i] = g_emb[b * 4864 + i];

    auto loadW = [&](float* dst, const float* src) {
        for (int i = tid; i < 4096; i += 256) dst[i] = __ldg(src + i);
    };
    auto lin = [&](const float* in, const float* W, const float* bias,
                   float* op, const float* resid) {
        for (int idx = tid; idx < 4864; idx += 256) {
            int ff = idx >> 6, hh = idx & 63;
            float acc = __ldg(bias + hh);
            const float* ip = in + ff * 64;
#pragma unroll 8
            for (int k = 0; k < 64; k++) acc = fmaf(ip[k], W[k * 64 + hh], acc);
            if (resid) acc += resid[idx];
            op[idx] = acc;
        }
    };

    loadW(sW, wq); __syncthreads();
    lin(sE, sW, bq, sA, nullptr); __syncthreads();
    loadW(sW, wk); __syncthreads();
    lin(sE, sW, bk, sB, nullptr); __syncthreads();
    loadW(sW, wv); __syncthreads();
    lin(sE, sW, bv, sC, nullptr); __syncthreads();

    for (int hd = 0; hd < 4; hd++) {
        int off = hd * 16;
        for (int idx = tid; idx < 5776; idx += 256) {
            int fq = idx / 76, fk = idx - fq * 76;
            float acc = 0.f;
#pragma unroll
            for (int d = 0; d < 16; d++)
                acc = fmaf(sA[fq * 64 + off + d], sB[fk * 64 + off + d], acc);
            sS[idx] = acc * 0.25f;
        }
        __syncthreads();
        if (tid < 76) {
            float m = -1e30f;
            for (int j = 0; j < 76; j++) m = fmaxf(m, sS[tid * 76 + j]);
            float s = 0.f;
            for (int j = 0; j < 76; j++) {
                float e = __expf(sS[tid * 76 + j] - m);
                sS[tid * 76 + j] = e; s += e;
            }
            float inv = __fdividef(1.f, s);
            for (int j = 0; j < 76; j++) sS[tid * 76 + j] *= inv;
        }
        __syncthreads();
        for (int idx = tid; idx < 1216; idx += 256) {
            int fq = idx >> 4, d = idx & 15;
            float acc = 0.f;
            for (int fk = 0; fk < 76; fk++)
                acc = fmaf(sS[fq * 76 + fk], sC[fk * 64 + off + d], acc);
            sA[fq * 64 + off + d] = acc;
        }
        __syncthreads();
    }

    loadW(sW, wo); __syncthreads();
    lin(sA, sW, bo, sB, sE); __syncthreads();

    for (int idx = tid; idx < 4864; idx += 256)
        sC[idx] = sB[idx] + __ldg(fb2 + (idx & 63));
    for (int cb = 0; cb < 4; cb++) {
        for (int i = tid; i < 4096; i += 256) {
            int k = i >> 6, j = i & 63;
            sW[i]  = __ldg(fw1 + k * 256 + cb * 64 + j);
            sW2[i] = __ldg(fw2 + (cb * 64 + k) * 64 + j);
        }
        __syncthreads();
        for (int idx = tid; idx < 4864; idx += 256) {
            int ff = idx >> 6, j = idx & 63;
            float acc = __ldg(fb1 + cb * 64 + j);
            const float* ip = sB + ff * 64;
#pragma unroll 8
            for (int k = 0; k < 64; k++) acc = fmaf(ip[k], sW[k * 64 + j], acc);
            sA[idx] = fmaxf(acc, 0.f);
        }
        __syncthreads();
        for (int idx = tid; idx < 4864; idx += 256) {
            int ff = idx >> 6, hh = idx & 63;
            float acc = 0.f;
            const float* ip = sA + ff * 64;
#pragma unroll 8
            for (int j = 0; j < 64; j++) acc = fmaf(ip[j], sW2[j * 64 + hh], acc);
            sC[idx] += acc;
        }
        __syncthreads();
    }

    if (tid < 64) {
        float acc = __ldg(fabq + tid);
        for (int k = 0; k < 64; k++)
            acc = fmaf(sC[75 * 64 + k], __ldg(faq + k * 64 + tid), acc);
        sFq[tid] = acc;
    }
    loadW(sW, fak); __syncthreads();
    lin(sC, sW, fabk, sA, nullptr); __syncthreads();
    loadW(sW, fav); __syncthreads();
    lin(sC, sW, fabv, sB, nullptr); __syncthreads();

    if (tid < 76) {
        float acc = 0.f;
        for (int hh = 0; hh < 64; hh++) acc = fmaf(sA[tid * 64 + hh], sFq[hh], acc);
        sFe[tid] = acc;
    }
    __syncthreads();
    if (tid == 0) {
        float m = -1e30f;
        for (int f2 = 0; f2 < 76; f2++) m = fmaxf(m, sFe[f2]);
        float s = 0.f;
        for (int f2 = 0; f2 < 76; f2++) {
            float e = __expf(sFe[f2] - m); sFe[f2] = e; s += e;
        }
        sFe[76] = __fdividef(1.f, s);
    }
    __syncthreads();
    if (tid < 64) {
        float acc = 0.f;
        for (int f2 = 0; f2 < 76; f2++) acc = fmaf(sFe[f2], sB[f2 * 64 + tid], acc);
        sV[tid] = acc * sFe[76];
    }
    __syncthreads();
    if (tid < 64) {
        float acc = __ldg(o0b + tid);
        for (int k = 0; k < 64; k++) acc = fmaf(sV[k], __ldg(o0w + k * 64 + tid), acc);
        sR[tid] = fmaxf(acc, 0.f);
    }
    __syncthreads();
    if (tid == 0) {
        float acc = __ldg(o1b);
        for (int hh = 0; hh < 64; hh++) acc = fmaf(sR[hh], __ldg(o1w + hh), acc);
        out[b] = sigf(acc);
    }
}

// ---------------------------------------------------------------------------
extern "C" void kernel_launch(void* const* d_in, const int* in_sizes, int n_in,
                              void* d_out, int out_size)
{
    const float* x      = (const float*)d_in[0];
    const float* w_ih   = (const float*)d_in[1];
    const float* w_hh   = (const float*)d_in[2];
    const float* b_ih   = (const float*)d_in[3];
    const float* b_hh   = (const float*)d_in[4];
    const float* att_Wt = (const float*)d_in[5];
    const float* att_Wx = (const float*)d_in[6];
    const float* att_rt = (const float*)d_in[7];
    const float* mwq = (const float*)d_in[8];   const float* mbq = (const float*)d_in[9];
    const float* mwk = (const float*)d_in[10];  const float* mbk = (const float*)d_in[11];
    const float* mwv = (const float*)d_in[12];  const float* mbv = (const float*)d_in[13];
    const float* mwo = (const float*)d_in[14];  const float* mbo = (const float*)d_in[15];
    const float* fw1 = (const float*)d_in[16];  const float* fb1 = (const float*)d_in[17];
    const float* fw2 = (const float*)d_in[18];  const float* fb2 = (const float*)d_in[19];
    const float* faq = (const float*)d_in[20];  const float* fabq = (const float*)d_in[21];
    const float* fak = (const float*)d_in[22];  const float* fabk = (const float*)d_in[23];
    const float* fav = (const float*)d_in[24];  const float* fabv = (const float*)d_in[25];
    const float* o0w = (const float*)d_in[26];  const float* o0b = (const float*)d_in[27];
    const float* o1w = (const float*)d_in[28];  const float* o1b = (const float*)d_in[29];
    float* out = (float*)d_out;

    cudaFuncSetAttribute(gru_mma, cudaFuncAttributeMaxDynamicSharedMemorySize, 131072);
    cudaFuncSetAttribute(mha_kernel, cudaFuncAttributeMaxDynamicSharedMemorySize, 139264);

    gru_mma<<<FF, 256, GRU_SMEM>>>(x, w_ih, w_hh, b_ih, b_hh);
    attn2<<<FF * 2, 256>>>(att_Wt, att_Wx, att_rt);
    mha_kernel<<<BB, 256, 134784>>>(mwq, mbq, mwk, mbk, mwv, mbv, mwo, mbo,
                                    fw1, fb1, fw2, fb2,
                                    faq, fabq, fak, fabk, fav, fabv,
                                    o0w, o0b, o1w, o1b, out);
}